// round 4
// baseline (speedup 1.0000x reference)
#include <cuda_runtime.h>

typedef unsigned long long ull;

#define TT 1024
#define BB 32
#define DD 768
#define LLn 48

// Scratch (static device globals — no allocation)
__device__ float g_em[TT * BB * LLn];   // emissions [T,B,L]
__device__ int   g_bool_dt;             // 0=uint8, 1=int32, 2=float32

__device__ __forceinline__ ull pack2(float x, float y) {
    ull r; asm("mov.b64 %0, {%1,%2};" : "=l"(r) : "f"(x), "f"(y)); return r;
}
__device__ __forceinline__ void unpack2(ull v, float& x, float& y) {
    asm("mov.b64 {%0,%1}, %2;" : "=f"(x), "=f"(y) : "l"(v));
}
__device__ __forceinline__ ull fma2(ull a, ull b, ull c) {
    ull d; asm("fma.rn.f32x2 %0, %1, %2, %3;" : "=l"(d) : "l"(a), "l"(b), "l"(c)); return d;
}
__device__ __forceinline__ ull add2(ull a, ull b) {
    ull d; asm("add.rn.f32x2 %0, %1, %2;" : "=l"(d) : "l"(a), "l"(b)); return d;
}

__device__ __forceinline__ int loadBool(const void* p, int dt, long idx) {
    if (dt == 1) return ((const int*)p)[idx] != 0;
    if (dt == 0) return ((const unsigned char*)p)[idx] != 0;
    return ((const float*)p)[idx] != 0.f;
}

// ---------------------------------------------------------------------------
// Detect boolean storage dtype from the tags buffer (~30% true rate).
// Parallel: 256 threads x 4 words, reduce via __syncthreads_or.
//   float32: some word == 0x3F800000 (1.0f)
//   uint8  : some word has nonzero bits above byte 0 (packed 0/1 bytes)
//   int32  : otherwise (all words 0 or 1)
// ---------------------------------------------------------------------------
__global__ void detect_kernel(const unsigned int* __restrict__ w) {
    int i = threadIdx.x;
    int f = 0, u = 0;
#pragma unroll
    for (int q = 0; q < 4; q++) {
        unsigned int v = w[i + q * 256];
        if (v == 0x3F800000u) f = 1;
        else if (v & 0xFFFFFF00u) u = 1;
    }
    int anyf = __syncthreads_or(f);
    int anyu = __syncthreads_or(u);
    if (i == 0) g_bool_dt = anyf ? 2 : (anyu ? 0 : 1);
}

// ---------------------------------------------------------------------------
// Emissions GEMM: em[t,b,j] = feats[t,b,:] . W[:,j] + bias[j]
// 32768 rows x 768 x 48. CTA = 256 rows, one row per thread.
// A staged through smem with coalesced global loads (K-tile = 32).
// Inner product via packed f32x2 FMA (2 MAC/instr).
// ---------------------------------------------------------------------------
#define KT 32
__global__ __launch_bounds__(256) void emis_kernel(const float* __restrict__ feats,
                                                   const float* __restrict__ W,
                                                   const float* __restrict__ bias) {
    __shared__ float2 As[256 * 17];       // 256 rows x (16 data f2 + 1 pad) = 34 KB
    __shared__ float  Ws[KT * LLn];       // 32 x 48 = 6 KB
    const int tid = threadIdx.x;
    const int base_row = blockIdx.x * 256;

    ull acc[24];
#pragma unroll
    for (int i = 0; i < 24; i++) acc[i] = 0ull;

    for (int kt = 0; kt < DD / KT; ++kt) {
        __syncthreads();  // protect previous tile reads
        // stage A tile: rows [base_row, base_row+256), K cols [kt*32, kt*32+32)
        // coalesced: warp covers two contiguous 128B row-segments
        {
            const float2* fg = (const float2*)(feats);
#pragma unroll
            for (int q = 0; q < 16; q++) {
                int n = q * 256 + tid;          // 0..4095
                int row = n >> 4;                // 16 f2 per row
                int c2  = n & 15;
                As[row * 17 + c2] = fg[(size_t)(base_row + row) * (DD / 2) + kt * (KT / 2) + c2];
            }
        }
        // stage W tile: rows kt*32..+32 (contiguous 6144B)
        {
            const float4* wg = (const float4*)(W + kt * KT * LLn);
            float4* ws4 = (float4*)Ws;
            for (int n = tid; n < KT * LLn / 4; n += 256) ws4[n] = wg[n];
        }
        __syncthreads();

        const float2* arow = As + tid * 17;
#pragma unroll
        for (int k2 = 0; k2 < 16; k2++) {
            float2 a2 = arow[k2];
            ull d0 = pack2(a2.x, a2.x);
            ull d1 = pack2(a2.y, a2.y);
            const ull* w0 = (const ull*)(Ws + (2 * k2) * LLn);
            const ull* w1 = (const ull*)(Ws + (2 * k2 + 1) * LLn);
#pragma unroll
            for (int jp = 0; jp < 24; jp++) {
                acc[jp] = fma2(d0, w0[jp], acc[jp]);
                acc[jp] = fma2(d1, w1[jp], acc[jp]);
            }
        }
    }
    float* orow = g_em + (size_t)(base_row + tid) * LLn;
#pragma unroll
    for (int jp = 0; jp < 24; jp++) {
        float x, y; unpack2(acc[jp], x, y);
        float2 o; o.x = x + bias[2 * jp]; o.y = y + bias[2 * jp + 1];
        ((float2*)orow)[jp] = o;
    }
}

// ---------------------------------------------------------------------------
// CRF forward scans in linear domain with carried log-offset c.
// One CTA per batch b: threads 0..63 = unconstrained chain, 64..127 = partial.
// Both chains have identical control flow (same len) -> shared __syncthreads.
// Threads g<48 of each group own label j=g; exp(trans[j,:]) in 24 packed regs.
// Writes out[b] = fwd - par directly.
// ---------------------------------------------------------------------------
__global__ __launch_bounds__(128) void scan_kernel(float* __restrict__ out,
                                                   const void* __restrict__ tags,
                                                   const int* __restrict__ lens,
                                                   const float* __restrict__ beg,
                                                   const float* __restrict__ trans,
                                                   const float* __restrict__ endv,
                                                   const void* __restrict__ bc,
                                                   const void* __restrict__ ec,
                                                   const void* __restrict__ tc) {
    __shared__ float ubuf[2][2][LLn];     // [group][phase][label]
    __shared__ float redbuf[2][LLn];
    __shared__ float res2[2];
    const int tid = threadIdx.x;
    const int grp = tid >> 6;             // 0 = fwd, 1 = par
    const int g = tid & 63;
    const int j = g;
    const bool is_par = (grp == 1);
    const bool active = g < LLn;
    const int b = blockIdx.x;
    const int lenm1 = lens[b] - 1;
    const int dt = g_bool_dt;

    ull E2[24];
    float Eend = 0.f;
    if (active) {
#pragma unroll
        for (int kp = 0; kp < 24; kp++) {
            float a0 = trans[j * LLn + 2 * kp];
            float a1 = trans[j * LLn + 2 * kp + 1];
            float e0 = __expf(a0), e1 = __expf(a1);
            if (is_par) {
                if (loadBool(tc, dt, j * LLn + 2 * kp))     e0 = 0.f;
                if (loadBool(tc, dt, j * LLn + 2 * kp + 1)) e1 = 0.f;
            }
            E2[kp] = pack2(e0, e1);
        }
        float ev = __expf(endv[j]);
        if (is_par && loadBool(ec, dt, j)) ev = 0.f;
        Eend = ev;
        // t = 0 init
        float x = g_em[b * LLn + j] + beg[j];
        float u0 = __expf(x);
        if (is_par) {
            if (loadBool(bc, dt, j) || loadBool(tags, dt, b * LLn + j)) u0 = 0.f;
        }
        ubuf[grp][0][j] = u0;
    }

    float c = 0.f;
    int rcnt = 8;
    int p = 0;
    int t = 1;
    bool fin = (lenm1 <= 0);

    auto emload = [&](int tt) -> float {
        int tq = (tt <= TT - 1) ? tt : (TT - 1);
        return active ? __ldg(&g_em[(tq * BB + b) * LLn + j]) : 0.f;
    };
    auto tgload = [&](int tt) -> int {
        int tq = (tt <= TT - 1) ? tt : (TT - 1);
        return (is_par && active) ? loadBool(tags, dt, (long)(tq * BB + b) * LLn + j) : 0;
    };

    auto do_step = [&](float PE, int PT) {
        __syncthreads();  // u[p] from previous step visible (both groups in lockstep)
        float unew = 0.f;
        if (active) {
            float Eem = __expf(PE);
            bool ren = (--rcnt == 0);
            const ulonglong2* uu = (const ulonglong2*)(ubuf[grp][p]);
            ull a0 = 0, a1 = 0, a2 = 0, a3 = 0;
#pragma unroll
            for (int i = 0; i < 6; i++) {
                ulonglong2 q0 = uu[2 * i];
                ulonglong2 q1 = uu[2 * i + 1];
                a0 = fma2(E2[4 * i],     q0.x, a0);
                a1 = fma2(E2[4 * i + 1], q0.y, a1);
                a2 = fma2(E2[4 * i + 2], q1.x, a2);
                a3 = fma2(E2[4 * i + 3], q1.y, a3);
            }
            a0 = add2(a0, a2); a1 = add2(a1, a3); a0 = add2(a0, a1);
            float lo, hi; unpack2(a0, lo, hi);
            float s = lo + hi;
            float scale = 1.f;
            if (ren) {
                rcnt = 8;
                const float4* u4 = (const float4*)(ubuf[grp][p]);
                float4 m4 = u4[0];
#pragma unroll
                for (int i = 1; i < 12; i++) {
                    float4 q = u4[i];
                    m4.x = fmaxf(m4.x, q.x); m4.y = fmaxf(m4.y, q.y);
                    m4.z = fmaxf(m4.z, q.z); m4.w = fmaxf(m4.w, q.w);
                }
                float m = fmaxf(fmaxf(m4.x, m4.y), fmaxf(m4.z, m4.w));
                m = fmaxf(m, 1e-35f);
                scale = __fdividef(1.f, m);
                c += logf(m);
            }
            float val = s * scale * Eem;
            if (is_par && PT) val = 0.f;
            ubuf[grp][p ^ 1][j] = val;
            unew = val;
        }
        if (t == lenm1) {  // uniform across CTA (both groups share len)
            if (active) redbuf[grp][j] = unew * Eend;
            __syncthreads();
            if (g == 0) {
                const float4* s4 = (const float4*)(redbuf[grp]);
                float acc0 = 0.f;
#pragma unroll
                for (int i = 0; i < 12; i++) {
                    float4 q = s4[i];
                    acc0 += (q.x + q.y) + (q.z + q.w);
                }
                res2[grp] = c + logf(acc0);
            }
            fin = true;
        }
        p ^= 1;
    };

    // depth-4 register prefetch pipeline for em/tags
    float peA = emload(1), peB = emload(2), peC = emload(3), peD = emload(4);
    int ptA = tgload(1), ptB = tgload(2), ptC = tgload(3), ptD = tgload(4);

    while (!fin) {
        do_step(peA, ptA); if (fin) break; peA = emload(t + 4); ptA = tgload(t + 4); ++t;
        do_step(peB, ptB); if (fin) break; peB = emload(t + 4); ptB = tgload(t + 4); ++t;
        do_step(peC, ptC); if (fin) break; peC = emload(t + 4); ptC = tgload(t + 4); ++t;
        do_step(peD, ptD); if (fin) break; peD = emload(t + 4); ptD = tgload(t + 4); ++t;
    }

    __syncthreads();
    if (tid == 0) out[b] = res2[0] - res2[1];
}

extern "C" void kernel_launch(void* const* d_in, const int* in_sizes, int n_in,
                              void* d_out, int out_size) {
    const float* feats = (const float*)d_in[0];
    const void*  tags  = d_in[1];
    const int*   lens  = (const int*)d_in[2];
    const float* W     = (const float*)d_in[3];
    const float* bias  = (const float*)d_in[4];
    const float* beg   = (const float*)d_in[5];
    const float* trans = (const float*)d_in[6];
    const float* endv  = (const float*)d_in[7];
    const void*  bc    = d_in[8];
    const void*  ec    = d_in[9];
    const void*  tc    = d_in[10];

    detect_kernel<<<1, 256>>>((const unsigned int*)tags);
    emis_kernel<<<128, 256>>>(feats, W, bias);
    scan_kernel<<<BB, 128>>>((float*)d_out, tags, lens, beg, trans, endv, bc, ec, tc);
}

// round 5
// speedup vs baseline: 1.0423x; 1.0423x over previous
#include <cuda_runtime.h>

typedef unsigned long long ull;

#define TT 1024
#define BB 32
#define DD 768
#define LLn 48

// Scratch (static device globals — no allocation)
__device__ float g_em[BB * TT * LLn];   // emissions re-laid as [b][t][l]
__device__ int   g_bool_dt;             // 0=uint8, 1=int32, 2=float32

__device__ __forceinline__ ull pack2(float x, float y) {
    ull r; asm("mov.b64 %0, {%1,%2};" : "=l"(r) : "f"(x), "f"(y)); return r;
}
__device__ __forceinline__ void unpack2(ull v, float& x, float& y) {
    asm("mov.b64 {%0,%1}, %2;" : "=f"(x), "=f"(y) : "l"(v));
}
__device__ __forceinline__ ull fma2(ull a, ull b, ull c) {
    ull d; asm("fma.rn.f32x2 %0, %1, %2, %3;" : "=l"(d) : "l"(a), "l"(b), "l"(c)); return d;
}
__device__ __forceinline__ ull add2(ull a, ull b) {
    ull d; asm("add.rn.f32x2 %0, %1, %2;" : "=l"(d) : "l"(a), "l"(b)); return d;
}

__device__ __forceinline__ int loadBool(const void* p, int dt, long idx) {
    if (dt == 1) return ((const int*)p)[idx] != 0;
    if (dt == 0) return ((const unsigned char*)p)[idx] != 0;
    return ((const float*)p)[idx] != 0.f;
}

// ---------------------------------------------------------------------------
// Detect boolean storage dtype from the tags buffer (~30% true rate).
// ---------------------------------------------------------------------------
__global__ void detect_kernel(const unsigned int* __restrict__ w) {
    int i = threadIdx.x;
    int f = 0, u = 0;
#pragma unroll
    for (int q = 0; q < 4; q++) {
        unsigned int v = w[i + q * 256];
        if (v == 0x3F800000u) f = 1;
        else if (v & 0xFFFFFF00u) u = 1;
    }
    int anyf = __syncthreads_or(f);
    int anyu = __syncthreads_or(u);
    if (i == 0) g_bool_dt = anyf ? 2 : (anyu ? 0 : 1);
}

// ---------------------------------------------------------------------------
// Emissions GEMM: em[b][t][j] = feats[t,b,:] . W[:,j] + bias[j]
// 32768 rows x 768 x 48. CTA = 256 rows, one row per thread.
// A staged through smem with coalesced global loads (K-tile = 32).
// ---------------------------------------------------------------------------
#define KT 32
__global__ __launch_bounds__(256) void emis_kernel(const float* __restrict__ feats,
                                                   const float* __restrict__ W,
                                                   const float* __restrict__ bias) {
    __shared__ float2 As[256 * 17];       // 256 rows x (16 data f2 + 1 pad) = 34 KB
    __shared__ float  Ws[KT * LLn];       // 32 x 48 = 6 KB
    const int tid = threadIdx.x;
    const int base_row = blockIdx.x * 256;

    ull acc[24];
#pragma unroll
    for (int i = 0; i < 24; i++) acc[i] = 0ull;

    for (int kt = 0; kt < DD / KT; ++kt) {
        __syncthreads();
        {
            const float2* fg = (const float2*)(feats);
#pragma unroll
            for (int q = 0; q < 16; q++) {
                int n = q * 256 + tid;
                int row = n >> 4;
                int c2  = n & 15;
                As[row * 17 + c2] = fg[(size_t)(base_row + row) * (DD / 2) + kt * (KT / 2) + c2];
            }
        }
        {
            const float4* wg = (const float4*)(W + kt * KT * LLn);
            float4* ws4 = (float4*)Ws;
            for (int n = tid; n < KT * LLn / 4; n += 256) ws4[n] = wg[n];
        }
        __syncthreads();

        const float2* arow = As + tid * 17;
#pragma unroll
        for (int k2 = 0; k2 < 16; k2++) {
            float2 a2 = arow[k2];
            ull d0 = pack2(a2.x, a2.x);
            ull d1 = pack2(a2.y, a2.y);
            const ull* w0 = (const ull*)(Ws + (2 * k2) * LLn);
            const ull* w1 = (const ull*)(Ws + (2 * k2 + 1) * LLn);
#pragma unroll
            for (int jp = 0; jp < 24; jp++) {
                acc[jp] = fma2(d0, w0[jp], acc[jp]);
                acc[jp] = fma2(d1, w1[jp], acc[jp]);
            }
        }
    }
    const int row = base_row + tid;
    const int b = row & (BB - 1);
    const int t = row >> 5;
    float* orow = g_em + ((size_t)b * TT + t) * LLn;
#pragma unroll
    for (int jp = 0; jp < 24; jp++) {
        float x, y; unpack2(acc[jp], x, y);
        float2 o; o.x = x + bias[2 * jp]; o.y = y + bias[2 * jp + 1];
        ((float2*)orow)[jp] = o;
    }
}

// ---------------------------------------------------------------------------
// CRF forward scan, warp-synchronous: ONE WARP per chain, NO CTA barriers in
// the loop. CTA b holds warp0 = unconstrained, warp1 = partial (independent).
// Lane l owns rows l and 32+l (rows >=48 padded with E=0 for lanes >=16).
// State u[48] in per-warp smem double buffer; renorm/final via shfl bfly.
// ---------------------------------------------------------------------------
__global__ __launch_bounds__(64) void scan_kernel(float* __restrict__ out,
                                                  const void* __restrict__ tags,
                                                  const int* __restrict__ lens,
                                                  const float* __restrict__ beg,
                                                  const float* __restrict__ trans,
                                                  const float* __restrict__ endv,
                                                  const void* __restrict__ bc,
                                                  const void* __restrict__ ec,
                                                  const void* __restrict__ tc) {
    __shared__ float ubuf[2][2][LLn];     // [warp][phase][label]
    __shared__ float wres[2];
    const int tid = threadIdx.x;
    const int w = tid >> 5;               // 0 = fwd, 1 = par
    const int l = tid & 31;
    const bool is_par = (w == 1);
    const bool hasB = l < 16;
    const int rB = 32 + l;                // second row (valid if hasB)
    const int b = blockIdx.x;
    const int lenm1 = lens[b] - 1;
    const int dt = g_bool_dt;
    const float* emb = g_em + (size_t)b * TT * LLn;

    // Transition rows in registers (exp'd, constraint-masked for par)
    ull EA[24], EB[24];
#pragma unroll
    for (int kp = 0; kp < 24; kp++) {
        float a0 = trans[l * LLn + 2 * kp];
        float a1 = trans[l * LLn + 2 * kp + 1];
        float e0 = __expf(a0), e1 = __expf(a1);
        if (is_par) {
            if (loadBool(tc, dt, l * LLn + 2 * kp))     e0 = 0.f;
            if (loadBool(tc, dt, l * LLn + 2 * kp + 1)) e1 = 0.f;
        }
        EA[kp] = pack2(e0, e1);
        float f0 = 0.f, f1 = 0.f;
        if (hasB) {
            f0 = __expf(trans[rB * LLn + 2 * kp]);
            f1 = __expf(trans[rB * LLn + 2 * kp + 1]);
            if (is_par) {
                if (loadBool(tc, dt, rB * LLn + 2 * kp))     f0 = 0.f;
                if (loadBool(tc, dt, rB * LLn + 2 * kp + 1)) f1 = 0.f;
            }
        }
        EB[kp] = pack2(f0, f1);
    }
    float EendA = __expf(endv[l]);
    if (is_par && loadBool(ec, dt, l)) EendA = 0.f;
    float EendB = 0.f;
    if (hasB) {
        EendB = __expf(endv[rB]);
        if (is_par && loadBool(ec, dt, rB)) EendB = 0.f;
    }

    // t = 0 init
    {
        float u0 = __expf(emb[l] + beg[l]);
        if (is_par && (loadBool(bc, dt, l) || loadBool(tags, dt, b * LLn + l))) u0 = 0.f;
        ubuf[w][0][l] = u0;
        if (hasB) {
            float u1 = __expf(emb[rB] + beg[rB]);
            if (is_par && (loadBool(bc, dt, rB) || loadBool(tags, dt, b * LLn + rB))) u1 = 0.f;
            ubuf[w][0][rB] = u1;
        }
    }
    __syncwarp();

    float c = 0.f;
    int rcnt = 8;
    int p = 0;
    int t = 1;
    bool fin = (lenm1 <= 0);

    auto emA = [&](int tt) -> float {
        int tq = (tt <= TT - 1) ? tt : (TT - 1);
        return __ldg(&emb[tq * LLn + l]);
    };
    auto emB = [&](int tt) -> float {
        int tq = (tt <= TT - 1) ? tt : (TT - 1);
        return hasB ? __ldg(&emb[tq * LLn + rB]) : 0.f;
    };
    auto tgA = [&](int tt) -> int {
        int tq = (tt <= TT - 1) ? tt : (TT - 1);
        return is_par ? loadBool(tags, dt, ((long)tq * BB + b) * LLn + l) : 0;
    };
    auto tgB = [&](int tt) -> int {
        int tq = (tt <= TT - 1) ? tt : (TT - 1);
        return (is_par && hasB) ? loadBool(tags, dt, ((long)tq * BB + b) * LLn + rB) : 0;
    };

    auto do_step = [&](float peA, float peB, int ptA, int ptB) {
        __syncwarp();  // previous step's u stores visible within warp
        const ulonglong2* uu = (const ulonglong2*)(ubuf[w][p]);
        ull aA0 = 0, aA1 = 0, aA2 = 0, aA3 = 0;
        ull aB0 = 0, aB1 = 0, aB2 = 0, aB3 = 0;
#pragma unroll
        for (int i = 0; i < 6; i++) {
            ulonglong2 q0 = uu[2 * i];
            ulonglong2 q1 = uu[2 * i + 1];
            aA0 = fma2(EA[4 * i],     q0.x, aA0);
            aA1 = fma2(EA[4 * i + 1], q0.y, aA1);
            aA2 = fma2(EA[4 * i + 2], q1.x, aA2);
            aA3 = fma2(EA[4 * i + 3], q1.y, aA3);
            aB0 = fma2(EB[4 * i],     q0.x, aB0);
            aB1 = fma2(EB[4 * i + 1], q0.y, aB1);
            aB2 = fma2(EB[4 * i + 2], q1.x, aB2);
            aB3 = fma2(EB[4 * i + 3], q1.y, aB3);
        }
        aA0 = add2(aA0, aA2); aA1 = add2(aA1, aA3); aA0 = add2(aA0, aA1);
        aB0 = add2(aB0, aB2); aB1 = add2(aB1, aB3); aB0 = add2(aB0, aB1);
        float xA, yA, xB, yB;
        unpack2(aA0, xA, yA); unpack2(aB0, xB, yB);
        float valA = (xA + yA) * __expf(peA);
        float valB = (xB + yB) * __expf(peB);
        if (is_par) {
            if (ptA) valA = 0.f;
            if (ptB) valB = 0.f;
        }
        if (--rcnt == 0) {  // amortized renormalization
            rcnt = 8;
            float m = fmaxf(valA, valB);
#pragma unroll
            for (int off = 16; off >= 1; off >>= 1)
                m = fmaxf(m, __shfl_xor_sync(0xffffffffu, m, off));
            m = fmaxf(m, 1e-30f);
            float inv = __fdividef(1.f, m);
            valA *= inv; valB *= inv;
            c += __logf(m);
        }
        ubuf[w][p ^ 1][l] = valA;
        if (hasB) ubuf[w][p ^ 1][rB] = valB;
        if (t == lenm1) {  // uniform per warp
            float s = valA * EendA + valB * EendB;
#pragma unroll
            for (int off = 16; off >= 1; off >>= 1)
                s += __shfl_xor_sync(0xffffffffu, s, off);
            if (l == 0) wres[w] = c + __logf(s);
            fin = true;
        }
        p ^= 1;
    };

    // depth-4 register prefetch pipeline for em/tags
    float eA0 = emA(1), eA1 = emA(2), eA2 = emA(3), eA3 = emA(4);
    float eB0 = emB(1), eB1 = emB(2), eB2 = emB(3), eB3 = emB(4);
    int   tA0 = tgA(1), tA1 = tgA(2), tA2 = tgA(3), tA3 = tgA(4);
    int   tB0 = tgB(1), tB1 = tgB(2), tB2 = tgB(3), tB3 = tgB(4);

    while (!fin) {
        do_step(eA0, eB0, tA0, tB0); if (fin) break;
        eA0 = emA(t + 4); eB0 = emB(t + 4); tA0 = tgA(t + 4); tB0 = tgB(t + 4); ++t;
        do_step(eA1, eB1, tA1, tB1); if (fin) break;
        eA1 = emA(t + 4); eB1 = emB(t + 4); tA1 = tgA(t + 4); tB1 = tgB(t + 4); ++t;
        do_step(eA2, eB2, tA2, tB2); if (fin) break;
        eA2 = emA(t + 4); eB2 = emB(t + 4); tA2 = tgA(t + 4); tB2 = tgB(t + 4); ++t;
        do_step(eA3, eB3, tA3, tB3); if (fin) break;
        eA3 = emA(t + 4); eB3 = emB(t + 4); tA3 = tgA(t + 4); tB3 = tgB(t + 4); ++t;
    }

    __syncthreads();  // single end-of-kernel join of the two warps
    if (tid == 0) out[b] = wres[0] - wres[1];
}

extern "C" void kernel_launch(void* const* d_in, const int* in_sizes, int n_in,
                              void* d_out, int out_size) {
    const float* feats = (const float*)d_in[0];
    const void*  tags  = d_in[1];
    const int*   lens  = (const int*)d_in[2];
    const float* W     = (const float*)d_in[3];
    const float* bias  = (const float*)d_in[4];
    const float* beg   = (const float*)d_in[5];
    const float* trans = (const float*)d_in[6];
    const float* endv  = (const float*)d_in[7];
    const void*  bc    = d_in[8];
    const void*  ec    = d_in[9];
    const void*  tc    = d_in[10];

    detect_kernel<<<1, 256>>>((const unsigned int*)tags);
    emis_kernel<<<128, 256>>>(feats, W, bias);
    scan_kernel<<<BB, 64>>>((float*)d_out, tags, lens, beg, trans, endv, bc, ec, tc);
}

// round 6
// speedup vs baseline: 1.0670x; 1.0237x over previous
#include <cuda_runtime.h>

typedef unsigned long long ull;

#define TT 1024
#define BB 32
#define DD 768
#define LLn 48

// Scratch (static device globals — no allocation)
__device__ float g_eem[TT * BB * LLn];  // exp(em + bias), layout [t][b][l]
__device__ int   g_bool_dt;             // 0=uint8, 1=int32, 2=float32

__device__ __forceinline__ ull pack2(float x, float y) {
    ull r; asm("mov.b64 %0, {%1,%2};" : "=l"(r) : "f"(x), "f"(y)); return r;
}
__device__ __forceinline__ void unpack2(ull v, float& x, float& y) {
    asm("mov.b64 {%0,%1}, %2;" : "=f"(x), "=f"(y) : "l"(v));
}
__device__ __forceinline__ ull fma2(ull a, ull b, ull c) {
    ull d; asm("fma.rn.f32x2 %0, %1, %2, %3;" : "=l"(d) : "l"(a), "l"(b), "l"(c)); return d;
}
__device__ __forceinline__ ull add2(ull a, ull b) {
    ull d; asm("add.rn.f32x2 %0, %1, %2;" : "=l"(d) : "l"(a), "l"(b)); return d;
}

__device__ __forceinline__ int loadBool(const void* p, int dt, long idx) {
    if (dt == 1) return ((const int*)p)[idx] != 0;
    if (dt == 0) return ((const unsigned char*)p)[idx] != 0;
    return ((const float*)p)[idx] != 0.f;
}

// ---------------------------------------------------------------------------
// Detect boolean storage dtype from the tags buffer (~30% true rate).
// ---------------------------------------------------------------------------
__global__ void detect_kernel(const unsigned int* __restrict__ w) {
    int i = threadIdx.x;
    int f = 0, u = 0;
#pragma unroll
    for (int q = 0; q < 4; q++) {
        unsigned int v = w[i + q * 256];
        if (v == 0x3F800000u) f = 1;
        else if (v & 0xFFFFFF00u) u = 1;
    }
    int anyf = __syncthreads_or(f);
    int anyu = __syncthreads_or(u);
    if (i == 0) g_bool_dt = anyf ? 2 : (anyu ? 0 : 1);
}

// ---------------------------------------------------------------------------
// Emissions GEMM + exp: eem[t][b][j] = exp(feats[t,b,:] . W[:,j] + bias[j])
// 32768 rows x 768 x 48. CTA = 256 rows, one row per thread.
// A staged through smem with coalesced global loads (K-tile = 32).
// ---------------------------------------------------------------------------
#define KT 32
__global__ __launch_bounds__(256) void emis_kernel(const float* __restrict__ feats,
                                                   const float* __restrict__ W,
                                                   const float* __restrict__ bias) {
    __shared__ float2 As[256 * 17];       // 256 rows x (16 data f2 + 1 pad) = 34 KB
    __shared__ float  Ws[KT * LLn];       // 32 x 48 = 6 KB
    const int tid = threadIdx.x;
    const int base_row = blockIdx.x * 256;

    ull acc[24];
#pragma unroll
    for (int i = 0; i < 24; i++) acc[i] = 0ull;

    for (int kt = 0; kt < DD / KT; ++kt) {
        __syncthreads();
        {
            const float2* fg = (const float2*)(feats);
#pragma unroll
            for (int q = 0; q < 16; q++) {
                int n = q * 256 + tid;
                int row = n >> 4;
                int c2  = n & 15;
                As[row * 17 + c2] = fg[(size_t)(base_row + row) * (DD / 2) + kt * (KT / 2) + c2];
            }
        }
        {
            const float4* wg = (const float4*)(W + kt * KT * LLn);
            float4* ws4 = (float4*)Ws;
            for (int n = tid; n < KT * LLn / 4; n += 256) ws4[n] = wg[n];
        }
        __syncthreads();

        const float2* arow = As + tid * 17;
#pragma unroll
        for (int k2 = 0; k2 < 16; k2++) {
            float2 a2 = arow[k2];
            ull d0 = pack2(a2.x, a2.x);
            ull d1 = pack2(a2.y, a2.y);
            const ull* w0 = (const ull*)(Ws + (2 * k2) * LLn);
            const ull* w1 = (const ull*)(Ws + (2 * k2 + 1) * LLn);
#pragma unroll
            for (int jp = 0; jp < 24; jp++) {
                acc[jp] = fma2(d0, w0[jp], acc[jp]);
                acc[jp] = fma2(d1, w1[jp], acc[jp]);
            }
        }
    }
    // Epilogue: add bias, exponentiate, store. Layout [t][b][l] (row = t*32+b).
    float* orow = g_eem + (size_t)(base_row + tid) * LLn;
#pragma unroll
    for (int jp = 0; jp < 24; jp++) {
        float x, y; unpack2(acc[jp], x, y);
        float2 o;
        o.x = __expf(x + bias[2 * jp]);
        o.y = __expf(y + bias[2 * jp + 1]);
        ((float2*)orow)[jp] = o;
    }
}

// ---------------------------------------------------------------------------
// CRF forward scan, warp-synchronous: ONE WARP per chain, no CTA barriers in
// the loop. CTA b: warp0 = unconstrained, warp1 = partial (independent).
// Lane l owns rows l and 32+l (rows >=48 padded with E=0 for lanes >=16).
// Emissions arrive pre-exponentiated (eem) -> no MUFU in the step loop.
// ---------------------------------------------------------------------------
__global__ __launch_bounds__(64) void scan_kernel(float* __restrict__ out,
                                                  const void* __restrict__ tags,
                                                  const int* __restrict__ lens,
                                                  const float* __restrict__ beg,
                                                  const float* __restrict__ trans,
                                                  const float* __restrict__ endv,
                                                  const void* __restrict__ bc,
                                                  const void* __restrict__ ec,
                                                  const void* __restrict__ tc) {
    __shared__ float ubuf[2][2][LLn];     // [warp][phase][label]
    __shared__ float wres[2];
    const int tid = threadIdx.x;
    const int w = tid >> 5;               // 0 = fwd, 1 = par
    const int l = tid & 31;
    const bool is_par = (w == 1);
    const bool hasB = l < 16;
    const int rB = 32 + l;
    const int b = blockIdx.x;
    const int lenm1 = lens[b] - 1;
    const int dt = g_bool_dt;

    // Transition rows in registers (exp'd, constraint-masked for par)
    ull EA[24], EB[24];
#pragma unroll
    for (int kp = 0; kp < 24; kp++) {
        float a0 = trans[l * LLn + 2 * kp];
        float a1 = trans[l * LLn + 2 * kp + 1];
        float e0 = __expf(a0), e1 = __expf(a1);
        if (is_par) {
            if (loadBool(tc, dt, l * LLn + 2 * kp))     e0 = 0.f;
            if (loadBool(tc, dt, l * LLn + 2 * kp + 1)) e1 = 0.f;
        }
        EA[kp] = pack2(e0, e1);
        float f0 = 0.f, f1 = 0.f;
        if (hasB) {
            f0 = __expf(trans[rB * LLn + 2 * kp]);
            f1 = __expf(trans[rB * LLn + 2 * kp + 1]);
            if (is_par) {
                if (loadBool(tc, dt, rB * LLn + 2 * kp))     f0 = 0.f;
                if (loadBool(tc, dt, rB * LLn + 2 * kp + 1)) f1 = 0.f;
            }
        }
        EB[kp] = pack2(f0, f1);
    }
    float EendA = __expf(endv[l]);
    if (is_par && loadBool(ec, dt, l)) EendA = 0.f;
    float EendB = 0.f;
    if (hasB) {
        EendB = __expf(endv[rB]);
        if (is_par && loadBool(ec, dt, rB)) EendB = 0.f;
    }

    // t = 0 init: u0 = eem0 * exp(beg), masked for par
    {
        float u0 = g_eem[b * LLn + l] * __expf(beg[l]);
        if (is_par && (loadBool(bc, dt, l) || loadBool(tags, dt, b * LLn + l))) u0 = 0.f;
        ubuf[w][0][l] = u0;
        if (hasB) {
            float u1 = g_eem[b * LLn + rB] * __expf(beg[rB]);
            if (is_par && (loadBool(bc, dt, rB) || loadBool(tags, dt, b * LLn + rB))) u1 = 0.f;
            ubuf[w][0][rB] = u1;
        }
    }
    __syncwarp();

    float c = 0.f;
    int rcnt = 8;
    int p = 0;
    int t = 1;
    bool fin = (lenm1 <= 0);

    auto emA = [&](int tt) -> float {
        int tq = (tt <= TT - 1) ? tt : (TT - 1);
        return __ldg(&g_eem[((long)tq * BB + b) * LLn + l]);
    };
    auto emB = [&](int tt) -> float {
        int tq = (tt <= TT - 1) ? tt : (TT - 1);
        return hasB ? __ldg(&g_eem[((long)tq * BB + b) * LLn + rB]) : 0.f;
    };
    auto tgA = [&](int tt) -> int {
        int tq = (tt <= TT - 1) ? tt : (TT - 1);
        return is_par ? loadBool(tags, dt, ((long)tq * BB + b) * LLn + l) : 0;
    };
    auto tgB = [&](int tt) -> int {
        int tq = (tt <= TT - 1) ? tt : (TT - 1);
        return (is_par && hasB) ? loadBool(tags, dt, ((long)tq * BB + b) * LLn + rB) : 0;
    };

    auto do_step = [&](float peA, float peB, int ptA, int ptB) {
        __syncwarp();
        const ulonglong2* uu = (const ulonglong2*)(ubuf[w][p]);
        ull aA0 = 0, aA1 = 0, aA2 = 0, aA3 = 0;
        ull aB0 = 0, aB1 = 0, aB2 = 0, aB3 = 0;
#pragma unroll
        for (int i = 0; i < 6; i++) {
            ulonglong2 q0 = uu[2 * i];
            ulonglong2 q1 = uu[2 * i + 1];
            aA0 = fma2(EA[4 * i],     q0.x, aA0);
            aA1 = fma2(EA[4 * i + 1], q0.y, aA1);
            aA2 = fma2(EA[4 * i + 2], q1.x, aA2);
            aA3 = fma2(EA[4 * i + 3], q1.y, aA3);
            aB0 = fma2(EB[4 * i],     q0.x, aB0);
            aB1 = fma2(EB[4 * i + 1], q0.y, aB1);
            aB2 = fma2(EB[4 * i + 2], q1.x, aB2);
            aB3 = fma2(EB[4 * i + 3], q1.y, aB3);
        }
        aA0 = add2(aA0, aA2); aA1 = add2(aA1, aA3); aA0 = add2(aA0, aA1);
        aB0 = add2(aB0, aB2); aB1 = add2(aB1, aB3); aB0 = add2(aB0, aB1);
        float xA, yA, xB, yB;
        unpack2(aA0, xA, yA); unpack2(aB0, xB, yB);
        float valA = (xA + yA) * peA;          // peA = exp(em) precomputed
        float valB = (xB + yB) * peB;
        if (is_par) {
            if (ptA) valA = 0.f;
            if (ptB) valB = 0.f;
        }
        if (--rcnt == 0) {  // amortized renormalization
            rcnt = 8;
            float m = fmaxf(valA, valB);
#pragma unroll
            for (int off = 16; off >= 1; off >>= 1)
                m = fmaxf(m, __shfl_xor_sync(0xffffffffu, m, off));
            m = fmaxf(m, 1e-30f);
            float inv = __fdividef(1.f, m);
            valA *= inv; valB *= inv;
            c += __logf(m);
        }
        ubuf[w][p ^ 1][l] = valA;
        if (hasB) ubuf[w][p ^ 1][rB] = valB;
        if (t == lenm1) {  // uniform per warp
            float s = valA * EendA + valB * EendB;
#pragma unroll
            for (int off = 16; off >= 1; off >>= 1)
                s += __shfl_xor_sync(0xffffffffu, s, off);
            if (l == 0) wres[w] = c + __logf(s);
            fin = true;
        }
        p ^= 1;
    };

    // depth-4 register prefetch pipeline for eem/tags
    float eA0 = emA(1), eA1 = emA(2), eA2 = emA(3), eA3 = emA(4);
    float eB0 = emB(1), eB1 = emB(2), eB2 = emB(3), eB3 = emB(4);
    int   tA0 = tgA(1), tA1 = tgA(2), tA2 = tgA(3), tA3 = tgA(4);
    int   tB0 = tgB(1), tB1 = tgB(2), tB2 = tgB(3), tB3 = tgB(4);

    while (!fin) {
        do_step(eA0, eB0, tA0, tB0); if (fin) break;
        eA0 = emA(t + 4); eB0 = emB(t + 4); tA0 = tgA(t + 4); tB0 = tgB(t + 4); ++t;
        do_step(eA1, eB1, tA1, tB1); if (fin) break;
        eA1 = emA(t + 4); eB1 = emB(t + 4); tA1 = tgA(t + 4); tB1 = tgB(t + 4); ++t;
        do_step(eA2, eB2, tA2, tB2); if (fin) break;
        eA2 = emA(t + 4); eB2 = emB(t + 4); tA2 = tgA(t + 4); tB2 = tgB(t + 4); ++t;
        do_step(eA3, eB3, tA3, tB3); if (fin) break;
        eA3 = emA(t + 4); eB3 = emB(t + 4); tA3 = tgA(t + 4); tB3 = tgB(t + 4); ++t;
    }

    __syncthreads();  // single end-of-kernel join of the two warps
    if (tid == 0) out[b] = wres[0] - wres[1];
}

extern "C" void kernel_launch(void* const* d_in, const int* in_sizes, int n_in,
                              void* d_out, int out_size) {
    const float* feats = (const float*)d_in[0];
    const void*  tags  = d_in[1];
    const int*   lens  = (const int*)d_in[2];
    const float* W     = (const float*)d_in[3];
    const float* bias  = (const float*)d_in[4];
    const float* beg   = (const float*)d_in[5];
    const float* trans = (const float*)d_in[6];
    const float* endv  = (const float*)d_in[7];
    const void*  bc    = d_in[8];
    const void*  ec    = d_in[9];
    const void*  tc    = d_in[10];

    // emis first so the ncu capture slot (launch #1) profiles the GEMM
    emis_kernel<<<128, 256>>>(feats, W, bias);
    detect_kernel<<<1, 256>>>((const unsigned int*)tags);
    scan_kernel<<<BB, 64>>>((float*)d_out, tags, lens, beg, trans, endv, bc, ec, tc);
}

// round 7
// speedup vs baseline: 1.4394x; 1.3490x over previous
#include <cuda_runtime.h>

typedef unsigned long long ull;

#define TT 1024
#define BB 32
#define DD 768
#define LLn 48

// Scratch (static device globals — no allocation)
__device__ float g_eem[TT * BB * LLn];  // exp(em + bias), layout [t][b][l]
__device__ int   g_bool_dt;             // 0=uint8, 1=int32, 2=float32

__device__ __forceinline__ ull pack2(float x, float y) {
    ull r; asm("mov.b64 %0, {%1,%2};" : "=l"(r) : "f"(x), "f"(y)); return r;
}
__device__ __forceinline__ void unpack2(ull v, float& x, float& y) {
    asm("mov.b64 {%0,%1}, %2;" : "=f"(x), "=f"(y) : "l"(v));
}
__device__ __forceinline__ ull fma2(ull a, ull b, ull c) {
    ull d; asm("fma.rn.f32x2 %0, %1, %2, %3;" : "=l"(d) : "l"(a), "l"(b), "l"(c)); return d;
}

__device__ __forceinline__ int loadBool(const void* p, int dt, long idx) {
    if (dt == 1) return ((const int*)p)[idx] != 0;
    if (dt == 0) return ((const unsigned char*)p)[idx] != 0;
    return ((const float*)p)[idx] != 0.f;
}

#define GBAR(id) asm volatile("bar.sync %0, 64;" :: "r"(id) : "memory")

// ---------------------------------------------------------------------------
// Detect boolean storage dtype from the tags buffer (~30% true rate).
// ---------------------------------------------------------------------------
__global__ void detect_kernel(const unsigned int* __restrict__ w) {
    int i = threadIdx.x;
    int f = 0, u = 0;
#pragma unroll
    for (int q = 0; q < 4; q++) {
        unsigned int v = w[i + q * 256];
        if (v == 0x3F800000u) f = 1;
        else if (v & 0xFFFFFF00u) u = 1;
    }
    int anyf = __syncthreads_or(f);
    int anyu = __syncthreads_or(u);
    if (i == 0) g_bool_dt = anyf ? 2 : (anyu ? 0 : 1);
}

// ---------------------------------------------------------------------------
// Emissions GEMM + exp: eem[t][b][j] = exp(feats[t,b,:] . W[:,j] + bias[j])
// 32768 rows x 768 x 48. CTA = 128 rows (128 threads), grid 256 -> ~2 CTA/SM.
// ---------------------------------------------------------------------------
#define KT 32
#define ROWS_PER_CTA 128
__global__ __launch_bounds__(ROWS_PER_CTA) void emis_kernel(const float* __restrict__ feats,
                                                            const float* __restrict__ W,
                                                            const float* __restrict__ bias) {
    __shared__ float2 As[ROWS_PER_CTA * 17];  // 128 rows x (16 f2 + pad) = 17 KB
    __shared__ float  Ws[KT * LLn];           // 32 x 48 = 6 KB
    const int tid = threadIdx.x;
    const int base_row = blockIdx.x * ROWS_PER_CTA;

    ull acc[24];
#pragma unroll
    for (int i = 0; i < 24; i++) acc[i] = 0ull;

    for (int kt = 0; kt < DD / KT; ++kt) {
        __syncthreads();
        {
            const float2* fg = (const float2*)(feats);
#pragma unroll
            for (int q = 0; q < 16; q++) {
                int n = q * ROWS_PER_CTA + tid;
                int row = n >> 4;
                int c2  = n & 15;
                As[row * 17 + c2] = fg[(size_t)(base_row + row) * (DD / 2) + kt * (KT / 2) + c2];
            }
        }
        {
            const float4* wg = (const float4*)(W + kt * KT * LLn);
            float4* ws4 = (float4*)Ws;
            for (int n = tid; n < KT * LLn / 4; n += ROWS_PER_CTA) ws4[n] = wg[n];
        }
        __syncthreads();

        const float2* arow = As + tid * 17;
#pragma unroll
        for (int k2 = 0; k2 < 16; k2++) {
            float2 a2 = arow[k2];
            ull d0 = pack2(a2.x, a2.x);
            ull d1 = pack2(a2.y, a2.y);
            const ull* w0 = (const ull*)(Ws + (2 * k2) * LLn);
            const ull* w1 = (const ull*)(Ws + (2 * k2 + 1) * LLn);
#pragma unroll
            for (int jp = 0; jp < 24; jp++) {
                acc[jp] = fma2(d0, w0[jp], acc[jp]);
                acc[jp] = fma2(d1, w1[jp], acc[jp]);
            }
        }
    }
    // Epilogue: add bias, exponentiate, store. Layout [t][b][l] (row = t*32+b).
    float* orow = g_eem + (size_t)(base_row + tid) * LLn;
#pragma unroll
    for (int jp = 0; jp < 24; jp++) {
        float x, y; unpack2(acc[jp], x, y);
        float2 o;
        o.x = __expf(x + bias[2 * jp]);
        o.y = __expf(y + bias[2 * jp + 1]);
        ((float2*)orow)[jp] = o;
    }
}

// ---------------------------------------------------------------------------
// CRF forward scan. CTA per batch b, 128 threads = 4 warps:
//   warps 0,1 = unconstrained chain (named barrier 1)
//   warps 2,3 = partial chain       (named barrier 2)
// Within a chain: warpA lane l -> row l, warpB lane l<16 -> row 32+l.
// One row per thread: 48 scalar FFMA + 12 LDS.128 per step, ~90 regs.
// Plain scalar math (no inline asm) so ptxas can batch loads and pipeline.
// ---------------------------------------------------------------------------
__global__ __launch_bounds__(128) void scan_kernel(float* __restrict__ out,
                                                   const void* __restrict__ tags,
                                                   const int* __restrict__ lens,
                                                   const float* __restrict__ beg,
                                                   const float* __restrict__ trans,
                                                   const float* __restrict__ endv,
                                                   const void* __restrict__ bc,
                                                   const void* __restrict__ ec,
                                                   const void* __restrict__ tc) {
    __shared__ float ubuf[2][2][LLn];   // [group][phase][label]
    __shared__ float wmax[2][2];        // [group][subwarp]
    __shared__ float wsum[2][2];
    __shared__ float wres[2];
    const int tid = threadIdx.x;
    const int warp = tid >> 5;
    const int grp = warp >> 1;          // 0 = fwd, 1 = par
    const int sub = warp & 1;           // 0 = rows 0..31, 1 = rows 32..47
    const int l = tid & 31;
    const bool is_par = (grp == 1);
    const bool rowvalid = (sub == 0) || (l < 16);
    const int row = rowvalid ? (sub * 32 + l) : 0;   // clamped for safe loads
    const int barid = grp + 1;
    const int b = blockIdx.x;
    const int lenm1 = lens[b] - 1;
    const int dt = g_bool_dt;

    // E row in 48 scalar registers (exp'd, constraint-masked for par)
    float E[LLn];
#pragma unroll
    for (int k = 0; k < LLn; k++) {
        float e = __expf(trans[row * LLn + k]);
        if (is_par && loadBool(tc, dt, row * LLn + k)) e = 0.f;
        E[k] = e;
    }
    float Eend = __expf(endv[row]);
    if (is_par && loadBool(ec, dt, row)) Eend = 0.f;

    // t = 0 init
    if (rowvalid) {
        float u0 = g_eem[b * LLn + row] * __expf(beg[row]);
        if (is_par && (loadBool(bc, dt, row) || loadBool(tags, dt, b * LLn + row))) u0 = 0.f;
        ubuf[grp][0][row] = u0;
    }
    GBAR(barid);

    float c = 0.f;
    int rcnt = 8;
    int p = 0;
    int t = 1;
    bool fin = false;

    auto emload = [&](int tt) -> float {
        int tq = (tt <= TT - 1) ? tt : (TT - 1);
        return __ldg(&g_eem[((long)tq * BB + b) * LLn + row]);
    };
    auto tgload = [&](int tt) -> int {
        int tq = (tt <= TT - 1) ? tt : (TT - 1);
        return is_par ? loadBool(tags, dt, ((long)tq * BB + b) * LLn + row) : 0;
    };

    auto do_step = [&](float pe, int pt) {
        const float4* uu = (const float4*)(ubuf[grp][p]);
        float a0 = 0.f, a1 = 0.f, a2 = 0.f, a3 = 0.f;
#pragma unroll
        for (int i = 0; i < 12; i++) {
            float4 q = uu[i];
            a0 = fmaf(E[4 * i],     q.x, a0);
            a1 = fmaf(E[4 * i + 1], q.y, a1);
            a2 = fmaf(E[4 * i + 2], q.z, a2);
            a3 = fmaf(E[4 * i + 3], q.w, a3);
        }
        float val = ((a0 + a1) + (a2 + a3)) * pe;
        if (is_par && pt) val = 0.f;
        if (!rowvalid) val = 0.f;

        if (--rcnt == 0) {  // amortized renormalization (every 8 steps)
            rcnt = 8;
            float m = val;
#pragma unroll
            for (int off = 16; off >= 1; off >>= 1)
                m = fmaxf(m, __shfl_xor_sync(0xffffffffu, m, off));
            if (l == 0) wmax[grp][sub] = m;
            GBAR(barid);
            float mm = fmaxf(fmaxf(wmax[grp][0], wmax[grp][1]), 1e-30f);
            val *= __fdividef(1.f, mm);
            c += __logf(mm);
        }
        if (rowvalid) ubuf[grp][p ^ 1][row] = val;

        if (t == lenm1) {   // uniform within group
            float s = rowvalid ? val * Eend : 0.f;
#pragma unroll
            for (int off = 16; off >= 1; off >>= 1)
                s += __shfl_xor_sync(0xffffffffu, s, off);
            if (l == 0) wsum[grp][sub] = s;
            GBAR(barid);
            if (l == 0 && sub == 0) wres[grp] = c + __logf(wsum[grp][0] + wsum[grp][1]);
            fin = true;
        }
        p ^= 1;
        GBAR(barid);        // u stores of this step visible before next step's loads
    };

    // depth-4 register prefetch pipeline for eem/tags
    float e0 = emload(1), e1 = emload(2), e2 = emload(3), e3 = emload(4);
    int   g0 = tgload(1), g1 = tgload(2), g2 = tgload(3), g3 = tgload(4);

    while (!fin) {
        do_step(e0, g0); if (fin) break; e0 = emload(t + 4); g0 = tgload(t + 4); ++t;
        do_step(e1, g1); if (fin) break; e1 = emload(t + 4); g1 = tgload(t + 4); ++t;
        do_step(e2, g2); if (fin) break; e2 = emload(t + 4); g2 = tgload(t + 4); ++t;
        do_step(e3, g3); if (fin) break; e3 = emload(t + 4); g3 = tgload(t + 4); ++t;
    }

    __syncthreads();  // join both groups
    if (tid == 0) out[b] = wres[0] - wres[1];
}

extern "C" void kernel_launch(void* const* d_in, const int* in_sizes, int n_in,
                              void* d_out, int out_size) {
    const float* feats = (const float*)d_in[0];
    const void*  tags  = d_in[1];
    const int*   lens  = (const int*)d_in[2];
    const float* W     = (const float*)d_in[3];
    const float* bias  = (const float*)d_in[4];
    const float* beg   = (const float*)d_in[5];
    const float* trans = (const float*)d_in[6];
    const float* endv  = (const float*)d_in[7];
    const void*  bc    = d_in[8];
    const void*  ec    = d_in[9];
    const void*  tc    = d_in[10];

    emis_kernel<<<256, ROWS_PER_CTA>>>(feats, W, bias);
    detect_kernel<<<1, 256>>>((const unsigned int*)tags);
    scan_kernel<<<BB, 128>>>((float*)d_out, tags, lens, beg, trans, endv, bc, ec, tc);
}

// round 8
// speedup vs baseline: 3.7065x; 2.5751x over previous
#include <cuda_runtime.h>

typedef unsigned long long ull;

#define TT 1024
#define BB 32
#define DD 768
#define LLn 48
#define SSTRIDE (BB * LLn)   // 1536 floats per time step

// Scratch (static device globals — no allocation)
__device__ float g_eem[TT * BB * LLn];   // exp(em + bias), layout [t][b][l]
__device__ float g_eemM[TT * BB * LLn];  // tags ? 0 : eem  (for partial chain)
__device__ float g_res[64];              // [0..31]=fwd, [32..63]=par
__device__ int   g_bool_dt;              // 0=uint8, 1=int32, 2=float32

__device__ __forceinline__ ull pack2(float x, float y) {
    ull r; asm("mov.b64 %0, {%1,%2};" : "=l"(r) : "f"(x), "f"(y)); return r;
}
__device__ __forceinline__ void unpack2(ull v, float& x, float& y) {
    asm("mov.b64 {%0,%1}, %2;" : "=f"(x), "=f"(y) : "l"(v));
}
__device__ __forceinline__ ull fma2(ull a, ull b, ull c) {
    ull d; asm("fma.rn.f32x2 %0, %1, %2, %3;" : "=l"(d) : "l"(a), "l"(b), "l"(c)); return d;
}
__device__ __forceinline__ ull add2(ull a, ull b) {
    ull d; asm("add.rn.f32x2 %0, %1, %2;" : "=l"(d) : "l"(a), "l"(b)); return d;
}

__device__ __forceinline__ int loadBool(const void* p, int dt, long idx) {
    if (dt == 1) return ((const int*)p)[idx] != 0;
    if (dt == 0) return ((const unsigned char*)p)[idx] != 0;
    return ((const float*)p)[idx] != 0.f;
}

// ---------------------------------------------------------------------------
// Detect boolean storage dtype from the tags buffer (~30% true rate).
// ---------------------------------------------------------------------------
__global__ void detect_kernel(const unsigned int* __restrict__ w) {
    int i = threadIdx.x;
    int f = 0, u = 0;
#pragma unroll
    for (int q = 0; q < 4; q++) {
        unsigned int v = w[i + q * 256];
        if (v == 0x3F800000u) f = 1;
        else if (v & 0xFFFFFF00u) u = 1;
    }
    int anyf = __syncthreads_or(f);
    int anyu = __syncthreads_or(u);
    if (i == 0) g_bool_dt = anyf ? 2 : (anyu ? 0 : 1);
}

// ---------------------------------------------------------------------------
// Emissions GEMM + exp: eem[t][b][j] = exp(feats[t,b,:].W[:,j] + bias[j])
// CTA = 256 threads = 128 rows x 2 column-halves (12 ull acc each, ~70 regs).
// ---------------------------------------------------------------------------
#define KT 32
__global__ __launch_bounds__(256) void emis_kernel(const float* __restrict__ feats,
                                                   const float* __restrict__ W,
                                                   const float* __restrict__ bias) {
    __shared__ float2 As[128 * 17];   // 128 rows x (16 f2 + pad) = 17 KB
    __shared__ float  Ws[KT * LLn];   // 32 x 48 = 6 KB
    const int tid = threadIdx.x;
    const int r = tid >> 1;           // row within CTA
    const int h = tid & 1;            // column half (0: j<24, 1: j>=24)
    const int base_row = blockIdx.x * 128;

    ull acc[12];
#pragma unroll
    for (int i = 0; i < 12; i++) acc[i] = 0ull;

    for (int kt = 0; kt < DD / KT; ++kt) {
        __syncthreads();
        {
            const float2* fg = (const float2*)(feats);
#pragma unroll
            for (int q = 0; q < 8; q++) {
                int n = q * 256 + tid;
                int rr = n >> 4;
                int c2 = n & 15;
                As[rr * 17 + c2] = fg[(size_t)(base_row + rr) * (DD / 2) + kt * (KT / 2) + c2];
            }
        }
        {
            const float4* wg = (const float4*)(W + kt * KT * LLn);
            float4* ws4 = (float4*)Ws;
            for (int n = tid; n < KT * LLn / 4; n += 256) ws4[n] = wg[n];
        }
        __syncthreads();

        const float2* arow = As + r * 17;
#pragma unroll
        for (int k2 = 0; k2 < 16; k2++) {
            float2 a2 = arow[k2];
            ull d0 = pack2(a2.x, a2.x);
            ull d1 = pack2(a2.y, a2.y);
            const ulonglong2* w0 = (const ulonglong2*)(Ws + (2 * k2) * LLn + h * 24);
            const ulonglong2* w1 = (const ulonglong2*)(Ws + (2 * k2 + 1) * LLn + h * 24);
#pragma unroll
            for (int j = 0; j < 6; j++) {
                ulonglong2 wa = w0[j];
                ulonglong2 wb = w1[j];
                acc[2 * j]     = fma2(d0, wa.x, acc[2 * j]);
                acc[2 * j + 1] = fma2(d0, wa.y, acc[2 * j + 1]);
                acc[2 * j]     = fma2(d1, wb.x, acc[2 * j]);
                acc[2 * j + 1] = fma2(d1, wb.y, acc[2 * j + 1]);
            }
        }
    }
    const int grow = base_row + r;       // = t*32 + b
    float* orow = g_eem + (size_t)grow * LLn + h * 24;
#pragma unroll
    for (int jp = 0; jp < 12; jp++) {
        float x, y; unpack2(acc[jp], x, y);
        float2 o;
        o.x = __expf(x + bias[h * 24 + 2 * jp]);
        o.y = __expf(y + bias[h * 24 + 2 * jp + 1]);
        ((float2*)orow)[jp] = o;
    }
}

// ---------------------------------------------------------------------------
// eemM = tags ? 0 : eem  (fully coalesced, float4/int4 vectorized)
// ---------------------------------------------------------------------------
__global__ __launch_bounds__(256) void mask_kernel(const void* __restrict__ tags) {
    int i = blockIdx.x * 256 + threadIdx.x;   // float4 index, 393216 total
    float4 e = ((const float4*)g_eem)[i];
    int dt = g_bool_dt;
    int b0, b1, b2, b3;
    if (dt == 1) {
        int4 t = ((const int4*)tags)[i];
        b0 = t.x != 0; b1 = t.y != 0; b2 = t.z != 0; b3 = t.w != 0;
    } else if (dt == 0) {
        uchar4 t = ((const uchar4*)tags)[i];
        b0 = t.x != 0; b1 = t.y != 0; b2 = t.z != 0; b3 = t.w != 0;
    } else {
        float4 t = ((const float4*)tags)[i];
        b0 = t.x != 0.f; b1 = t.y != 0.f; b2 = t.z != 0.f; b3 = t.w != 0.f;
    }
    if (b0) e.x = 0.f;
    if (b1) e.y = 0.f;
    if (b2) e.z = 0.f;
    if (b3) e.w = 0.f;
    ((float4*)g_eemM)[i] = e;
}

// ---------------------------------------------------------------------------
// CRF forward scan: one chain per 64-thread CTA (2 warps), grid 64.
// bidx 0..31 = unconstrained(b), 32..63 = partial(b). Thread owns one row:
// warp0 -> rows 0..31, warp1 lanes<16 -> rows 32..47.
// Per step: 12 LDS.128 + 24 packed fma2 + 1 LDG prefetch + __syncthreads.
// Masking is folded into eemM (pe == 0), so no per-step branches.
// ---------------------------------------------------------------------------
__global__ __launch_bounds__(64) void scan_kernel(const int* __restrict__ lens,
                                                  const float* __restrict__ beg,
                                                  const float* __restrict__ trans,
                                                  const float* __restrict__ endv,
                                                  const void* __restrict__ bc,
                                                  const void* __restrict__ ec,
                                                  const void* __restrict__ tc) {
    __shared__ __align__(16) float ubuf[2][LLn];
    __shared__ float wred[2];
    const int tid = threadIdx.x;
    const int sub = tid >> 5;
    const int l = tid & 31;
    const int bidx = blockIdx.x;
    const int b = bidx & 31;
    const bool is_par = bidx >= 32;
    const bool rowvalid = (sub == 0) || (l < 16);
    const int row = rowvalid ? sub * 32 + l : 0;   // clamped for safe loads
    const int lenm1 = lens[b] - 1;
    const int dt = g_bool_dt;
    const float* gb = (is_par ? g_eemM : g_eem) + b * LLn + row;

    // E row in 24 packed registers (exp'd, constraint-masked for par)
    ull E2[24];
#pragma unroll
    for (int kp = 0; kp < 24; kp++) {
        float e0 = __expf(trans[row * LLn + 2 * kp]);
        float e1 = __expf(trans[row * LLn + 2 * kp + 1]);
        if (is_par) {
            if (loadBool(tc, dt, row * LLn + 2 * kp))     e0 = 0.f;
            if (loadBool(tc, dt, row * LLn + 2 * kp + 1)) e1 = 0.f;
        }
        E2[kp] = pack2(e0, e1);
    }
    float Eend = __expf(endv[row]);
    if (is_par && loadBool(ec, dt, row)) Eend = 0.f;

    // t = 0 init (eemM already folds tags at t=0; bc applied here)
    if (rowvalid) {
        float u0 = __ldg(gb) * __expf(beg[row]);
        if (is_par && loadBool(bc, dt, row)) u0 = 0.f;
        ubuf[0][row] = u0;
    }
    __syncthreads();

    float c = 0.f;
    int rcnt = 8;
    int p = 0;
    int t = 1;
    bool fin = false;

    auto ld = [&](int tt) -> float {
        int tq = (tt <= TT - 1) ? tt : (TT - 1);
        return __ldg(gb + (size_t)tq * SSTRIDE);
    };

    auto do_step = [&](float pe) {
        const ulonglong2* uu = (const ulonglong2*)(ubuf[p]);
        ull a0 = 0, a1 = 0, a2 = 0, a3 = 0;
#pragma unroll
        for (int i = 0; i < 3; i++) {
            ulonglong2 q0 = uu[4 * i];
            ulonglong2 q1 = uu[4 * i + 1];
            ulonglong2 q2 = uu[4 * i + 2];
            ulonglong2 q3 = uu[4 * i + 3];
            a0 = fma2(E2[8 * i],     q0.x, a0);
            a1 = fma2(E2[8 * i + 1], q0.y, a1);
            a2 = fma2(E2[8 * i + 2], q1.x, a2);
            a3 = fma2(E2[8 * i + 3], q1.y, a3);
            a0 = fma2(E2[8 * i + 4], q2.x, a0);
            a1 = fma2(E2[8 * i + 5], q2.y, a1);
            a2 = fma2(E2[8 * i + 6], q3.x, a2);
            a3 = fma2(E2[8 * i + 7], q3.y, a3);
        }
        a0 = add2(a0, a2); a1 = add2(a1, a3); a0 = add2(a0, a1);
        float x, y; unpack2(a0, x, y);
        float val = (x + y) * pe;                // pe==0 encodes the tag mask

        if (--rcnt == 0) {  // amortized renormalization (every 8 steps)
            rcnt = 8;
            float m = val;
#pragma unroll
            for (int off = 16; off >= 1; off >>= 1)
                m = fmaxf(m, __shfl_xor_sync(0xffffffffu, m, off));
            if (l == 0) wred[sub] = m;
            __syncthreads();
            float mm = fmaxf(fmaxf(wred[0], wred[1]), 1e-30f);
            val *= __fdividef(1.f, mm);
            c += __logf(mm);
        }
        if (rowvalid) ubuf[p ^ 1][row] = val;

        if (t == lenm1) {   // uniform across CTA
            __syncthreads();
            float s = rowvalid ? val * Eend : 0.f;
#pragma unroll
            for (int off = 16; off >= 1; off >>= 1)
                s += __shfl_xor_sync(0xffffffffu, s, off);
            if (l == 0) wred[sub] = s;
            __syncthreads();
            if (tid == 0) g_res[bidx] = c + __logf(wred[0] + wred[1]);
            fin = true;
        }
        p ^= 1;
        __syncthreads();    // this step's stores visible before next step
    };

    // depth-4 register prefetch pipeline for emissions
    float e0 = ld(1), e1 = ld(2), e2 = ld(3), e3 = ld(4);

    while (!fin) {
        do_step(e0); if (fin) break; e0 = ld(t + 4); ++t;
        do_step(e1); if (fin) break; e1 = ld(t + 4); ++t;
        do_step(e2); if (fin) break; e2 = ld(t + 4); ++t;
        do_step(e3); if (fin) break; e3 = ld(t + 4); ++t;
    }
}

__global__ void combine_kernel(float* __restrict__ out) {
    int i = threadIdx.x;
    if (i < BB) out[i] = g_res[i] - g_res[BB + i];
}

extern "C" void kernel_launch(void* const* d_in, const int* in_sizes, int n_in,
                              void* d_out, int out_size) {
    const float* feats = (const float*)d_in[0];
    const void*  tags  = d_in[1];
    const int*   lens  = (const int*)d_in[2];
    const float* W     = (const float*)d_in[3];
    const float* bias  = (const float*)d_in[4];
    const float* beg   = (const float*)d_in[5];
    const float* trans = (const float*)d_in[6];
    const float* endv  = (const float*)d_in[7];
    const void*  bc    = d_in[8];
    const void*  ec    = d_in[9];
    const void*  tc    = d_in[10];

    emis_kernel<<<256, 256>>>(feats, W, bias);
    detect_kernel<<<1, 256>>>((const unsigned int*)tags);
    mask_kernel<<<TT * BB * LLn / 4 / 256, 256>>>(tags);
    scan_kernel<<<64, 64>>>(lens, beg, trans, endv, bc, ec, tc);
    combine_kernel<<<1, 32>>>((float*)d_out);
}

// round 9
// speedup vs baseline: 4.5419x; 1.2254x over previous
#include <cuda_runtime.h>

typedef unsigned long long ull;

#define TT 1024
#define BB 32
#define DD 768
#define LLn 48
#define SSTRIDE (BB * LLn)   // 1536 floats per time step

// Scratch (static device globals — no allocation)
__device__ float g_eem[TT * BB * LLn];   // exp(em + bias), layout [t][b][l]
__device__ float g_eemM[TT * BB * LLn];  // tags ? 0 : eem  (for partial chain)
__device__ float g_res[64];              // [0..31]=fwd, [32..63]=par
__device__ int   g_bool_dt;              // 0=uint8, 1=int32, 2=float32

__device__ __forceinline__ ull pack2(float x, float y) {
    ull r; asm("mov.b64 %0, {%1,%2};" : "=l"(r) : "f"(x), "f"(y)); return r;
}
__device__ __forceinline__ void unpack2(ull v, float& x, float& y) {
    asm("mov.b64 {%0,%1}, %2;" : "=f"(x), "=f"(y) : "l"(v));
}
__device__ __forceinline__ ull fma2(ull a, ull b, ull c) {
    ull d; asm("fma.rn.f32x2 %0, %1, %2, %3;" : "=l"(d) : "l"(a), "l"(b), "l"(c)); return d;
}
__device__ __forceinline__ ull add2(ull a, ull b) {
    ull d; asm("add.rn.f32x2 %0, %1, %2;" : "=l"(d) : "l"(a), "l"(b)); return d;
}

__device__ __forceinline__ int loadBool(const void* p, int dt, long idx) {
    if (dt == 1) return ((const int*)p)[idx] != 0;
    if (dt == 0) return ((const unsigned char*)p)[idx] != 0;
    return ((const float*)p)[idx] != 0.f;
}

// ---------------------------------------------------------------------------
// Detect boolean storage dtype from the tags buffer (~30% true rate).
// ---------------------------------------------------------------------------
__global__ void detect_kernel(const unsigned int* __restrict__ w) {
    int i = threadIdx.x;
    int f = 0, u = 0;
#pragma unroll
    for (int q = 0; q < 4; q++) {
        unsigned int v = w[i + q * 256];
        if (v == 0x3F800000u) f = 1;
        else if (v & 0xFFFFFF00u) u = 1;
    }
    int anyf = __syncthreads_or(f);
    int anyu = __syncthreads_or(u);
    if (i == 0) g_bool_dt = anyf ? 2 : (anyu ? 0 : 1);
}

// ---------------------------------------------------------------------------
// Emissions GEMM + exp: eem[t][b][j] = exp(feats[t,b,:].W[:,j] + bias[j])
// CTA = 256 threads = 128 rows x 2 column-halves (12 ull acc each).
// ---------------------------------------------------------------------------
#define KT 32
__global__ __launch_bounds__(256) void emis_kernel(const float* __restrict__ feats,
                                                   const float* __restrict__ W,
                                                   const float* __restrict__ bias) {
    __shared__ float2 As[128 * 17];   // 128 rows x (16 f2 + pad) = 17 KB
    __shared__ float  Ws[KT * LLn];   // 32 x 48 = 6 KB
    const int tid = threadIdx.x;
    const int r = tid >> 1;           // row within CTA
    const int h = tid & 1;            // column half (0: j<24, 1: j>=24)
    const int base_row = blockIdx.x * 128;

    ull acc[12];
#pragma unroll
    for (int i = 0; i < 12; i++) acc[i] = 0ull;

    for (int kt = 0; kt < DD / KT; ++kt) {
        __syncthreads();
        {
            const float2* fg = (const float2*)(feats);
#pragma unroll
            for (int q = 0; q < 8; q++) {
                int n = q * 256 + tid;
                int rr = n >> 4;
                int c2 = n & 15;
                As[rr * 17 + c2] = fg[(size_t)(base_row + rr) * (DD / 2) + kt * (KT / 2) + c2];
            }
        }
        {
            const float4* wg = (const float4*)(W + kt * KT * LLn);
            float4* ws4 = (float4*)Ws;
            for (int n = tid; n < KT * LLn / 4; n += 256) ws4[n] = wg[n];
        }
        __syncthreads();

        const float2* arow = As + r * 17;
#pragma unroll
        for (int k2 = 0; k2 < 16; k2++) {
            float2 a2 = arow[k2];
            ull d0 = pack2(a2.x, a2.x);
            ull d1 = pack2(a2.y, a2.y);
            const ulonglong2* w0 = (const ulonglong2*)(Ws + (2 * k2) * LLn + h * 24);
            const ulonglong2* w1 = (const ulonglong2*)(Ws + (2 * k2 + 1) * LLn + h * 24);
#pragma unroll
            for (int j = 0; j < 6; j++) {
                ulonglong2 wa = w0[j];
                ulonglong2 wb = w1[j];
                acc[2 * j]     = fma2(d0, wa.x, acc[2 * j]);
                acc[2 * j + 1] = fma2(d0, wa.y, acc[2 * j + 1]);
                acc[2 * j]     = fma2(d1, wb.x, acc[2 * j]);
                acc[2 * j + 1] = fma2(d1, wb.y, acc[2 * j + 1]);
            }
        }
    }
    const int grow = base_row + r;       // = t*32 + b
    float* orow = g_eem + (size_t)grow * LLn + h * 24;
#pragma unroll
    for (int jp = 0; jp < 12; jp++) {
        float x, y; unpack2(acc[jp], x, y);
        float2 o;
        o.x = __expf(x + bias[h * 24 + 2 * jp]);
        o.y = __expf(y + bias[h * 24 + 2 * jp + 1]);
        ((float2*)orow)[jp] = o;
    }
}

// ---------------------------------------------------------------------------
// eemM = tags ? 0 : eem  (fully coalesced, float4/int4 vectorized)
// ---------------------------------------------------------------------------
__global__ __launch_bounds__(256) void mask_kernel(const void* __restrict__ tags) {
    int i = blockIdx.x * 256 + threadIdx.x;   // float4 index
    float4 e = ((const float4*)g_eem)[i];
    int dt = g_bool_dt;
    int b0, b1, b2, b3;
    if (dt == 1) {
        int4 t = ((const int4*)tags)[i];
        b0 = t.x != 0; b1 = t.y != 0; b2 = t.z != 0; b3 = t.w != 0;
    } else if (dt == 0) {
        uchar4 t = ((const uchar4*)tags)[i];
        b0 = t.x != 0; b1 = t.y != 0; b2 = t.z != 0; b3 = t.w != 0;
    } else {
        float4 t = ((const float4*)tags)[i];
        b0 = t.x != 0.f; b1 = t.y != 0.f; b2 = t.z != 0.f; b3 = t.w != 0.f;
    }
    if (b0) e.x = 0.f;
    if (b1) e.y = 0.f;
    if (b2) e.z = 0.f;
    if (b3) e.w = 0.f;
    ((float4*)g_eemM)[i] = e;
}

// ---------------------------------------------------------------------------
// CRF forward scan, branch-free step bodies.
// One chain per 64-thread CTA, grid 64 (bidx<32: fwd, else par).
// Thread owns one row: warp0 -> rows 0..31, warp1 lanes<16 -> rows 32..47;
// warp1 lanes>=16 compute row 0 duplicates and store to dummy rows 48..63.
// Main loop: fully-unrolled groups of 8 steps; renorm at static slot 7;
// no length check inside (trip count = lenm1); tail + final after the loop.
// ---------------------------------------------------------------------------
__global__ __launch_bounds__(64) void scan_kernel(const int* __restrict__ lens,
                                                  const float* __restrict__ beg,
                                                  const float* __restrict__ trans,
                                                  const float* __restrict__ endv,
                                                  const void* __restrict__ bc,
                                                  const void* __restrict__ ec,
                                                  const void* __restrict__ tc) {
    __shared__ __align__(16) float ubuf[2][64];  // rows 48..63 are dummies
    __shared__ float wred[2];
    const int tid = threadIdx.x;
    const int sub = tid >> 5;
    const int l = tid & 31;
    const int bidx = blockIdx.x;
    const int b = bidx & 31;
    const bool is_par = bidx >= 32;
    const bool rowvalid = (sub == 0) || (l < 16);
    const int row = rowvalid ? sub * 32 + l : 0;  // clamped for safe loads
    const int srow = sub * 32 + l;                // store row (48..63 dummy)
    const int lenm1 = lens[b] - 1;
    const int dt = g_bool_dt;
    const float* gb = (is_par ? g_eemM : g_eem) + b * LLn + row;

    // E row in 24 packed registers (exp'd, constraint-masked for par)
    ull E2[24];
#pragma unroll
    for (int kp = 0; kp < 24; kp++) {
        float e0 = __expf(trans[row * LLn + 2 * kp]);
        float e1 = __expf(trans[row * LLn + 2 * kp + 1]);
        if (is_par) {
            if (loadBool(tc, dt, row * LLn + 2 * kp))     e0 = 0.f;
            if (loadBool(tc, dt, row * LLn + 2 * kp + 1)) e1 = 0.f;
        }
        E2[kp] = pack2(e0, e1);
    }
    float Eend = __expf(endv[row]);
    if (is_par && loadBool(ec, dt, row)) Eend = 0.f;
    if (!rowvalid) Eend = 0.f;   // excludes dummy lanes from the final sum

    // t = 0 init (eemM already folds tags; bc applied here)
    {
        float u0 = __ldg(gb) * __expf(beg[row]);
        if (is_par && loadBool(bc, dt, row)) u0 = 0.f;
        ubuf[0][srow] = rowvalid ? u0 : 0.f;
    }
    __syncthreads();

    float c = 0.f;
    int p = 0;
    int t = 1;

    auto ld = [&](int tt) -> float {
        int tq = (tt <= TT - 1) ? tt : (TT - 1);
        return __ldg(gb + (size_t)tq * SSTRIDE);
    };

    auto dot = [&]() -> float {
        const ulonglong2* uu = (const ulonglong2*)(ubuf[p]);
        ull a0 = 0, a1 = 0, a2 = 0, a3 = 0;
#pragma unroll
        for (int i = 0; i < 3; i++) {
            ulonglong2 q0 = uu[4 * i];
            ulonglong2 q1 = uu[4 * i + 1];
            ulonglong2 q2 = uu[4 * i + 2];
            ulonglong2 q3 = uu[4 * i + 3];
            a0 = fma2(E2[8 * i],     q0.x, a0);
            a1 = fma2(E2[8 * i + 1], q0.y, a1);
            a2 = fma2(E2[8 * i + 2], q1.x, a2);
            a3 = fma2(E2[8 * i + 3], q1.y, a3);
            a0 = fma2(E2[8 * i + 4], q2.x, a0);
            a1 = fma2(E2[8 * i + 5], q2.y, a1);
            a2 = fma2(E2[8 * i + 6], q3.x, a2);
            a3 = fma2(E2[8 * i + 7], q3.y, a3);
        }
        a0 = add2(a0, a2); a1 = add2(a1, a3); a0 = add2(a0, a1);
        float x, y; unpack2(a0, x, y);
        return x + y;
    };

    // rotating 8-slot emission prefetch (static indices -> stays in regs)
    float e[8];
#pragma unroll
    for (int i = 0; i < 8; i++) e[i] = ld(1 + i);

    // ---- main loop: groups of 8 branch-free steps, renorm at slot 7 ----
    while (t + 8 <= lenm1) {
#pragma unroll
        for (int i = 0; i < 8; i++) {
            float pe = e[i];
            e[i] = ld(t + 8 + i);            // prefetch same slot, next group
            float val = dot() * pe;
            if (i == 7) {                    // compile-time slot: branch-free
                float m = val;
#pragma unroll
                for (int off = 16; off >= 1; off >>= 1)
                    m = fmaxf(m, __shfl_xor_sync(0xffffffffu, m, off));
                if (l == 0) wred[sub] = m;
                __syncthreads();
                float mm = fmaxf(fmaxf(wred[0], wred[1]), 1e-30f);
                val *= __fdividef(1.f, mm);
                c += __logf(mm);
            }
            ubuf[p ^ 1][srow] = val;
            p ^= 1;
            __syncthreads();
        }
        t += 8;
    }

    // ---- tail: r plain steps (r in [0,7]), then the final step ----
    const int r = lenm1 - t;
    float efin = e[0];
#pragma unroll
    for (int i = 0; i < 8; i++) if (i == r) efin = e[i];

#pragma unroll
    for (int i = 0; i < 7; i++) {
        if (i < r) {
            float val = dot() * e[i];
            ubuf[p ^ 1][srow] = val;
            p ^= 1;
            __syncthreads();
        }
    }

    // final step (t == lenm1): emission + end transition + logsumexp readout
    {
        float val = dot() * efin;
        float s = val * Eend;                // Eend==0 on dummy lanes
#pragma unroll
        for (int off = 16; off >= 1; off >>= 1)
            s += __shfl_xor_sync(0xffffffffu, s, off);
        if (l == 0) wred[sub] = s;
        __syncthreads();
        if (tid == 0) g_res[bidx] = c + __logf(wred[0] + wred[1]);
    }
}

__global__ void combine_kernel(float* __restrict__ out) {
    int i = threadIdx.x;
    if (i < BB) out[i] = g_res[i] - g_res[BB + i];
}

extern "C" void kernel_launch(void* const* d_in, const int* in_sizes, int n_in,
                              void* d_out, int out_size) {
    const float* feats = (const float*)d_in[0];
    const void*  tags  = d_in[1];
    const int*   lens  = (const int*)d_in[2];
    const float* W     = (const float*)d_in[3];
    const float* bias  = (const float*)d_in[4];
    const float* beg   = (const float*)d_in[5];
    const float* trans = (const float*)d_in[6];
    const float* endv  = (const float*)d_in[7];
    const void*  bc    = d_in[8];
    const void*  ec    = d_in[9];
    const void*  tc    = d_in[10];

    emis_kernel<<<256, 256>>>(feats, W, bias);
    detect_kernel<<<1, 256>>>((const unsigned int*)tags);
    mask_kernel<<<TT * BB * LLn / 4 / 256, 256>>>(tags);
    scan_kernel<<<64, 64>>>(lens, beg, trans, endv, bc, ec, tc);
    combine_kernel<<<1, 32>>>((float*)d_out);
}